// round 15
// baseline (speedup 1.0000x reference)
#include <cuda_runtime.h>
#include <cuda_fp16.h>
#include <cuda_bf16.h>
#include <cstdint>
#include <cstddef>

// ----------------------------------------------------------------------------
// Problem constants
// ----------------------------------------------------------------------------
#define TOKENS 16384
#define DIN    2048
#define DOUT   2048

// ----------------------------------------------------------------------------
// Scratch (device globals — no allocation allowed)
// ----------------------------------------------------------------------------
__device__ __align__(16) __half g_xh[(size_t)TOKENS * DIN];   // x in fp16      (64 MB)
__device__ __align__(16) __half g_wt[(size_t)DOUT * DIN];     // W^T fp16 [N,K] ( 8 MB)
__device__ int g_xdtype;   // 0 = float32, 1 = bf16
__device__ int g_wdtype;   // 0 = int8, 1 = int32, 2 = float32, 3 = bf16

// ----------------------------------------------------------------------------
// Helpers
// ----------------------------------------------------------------------------
__device__ __forceinline__ uint32_t smem_u32(const void* p) {
    uint32_t a;
    asm("{ .reg .u64 t; cvta.to.shared.u64 t, %1; cvt.u32.u64 %0, t; }" : "=r"(a) : "l"(p));
    return a;
}
__device__ __forceinline__ void cpasync16(uint32_t s, const void* g) {
    asm volatile("cp.async.cg.shared.global [%0], [%1], 16;"
                 :: "r"(s), "l"(__cvta_generic_to_global(g)));
}
#define CP_COMMIT() asm volatile("cp.async.commit_group;" ::: "memory")
#define CP_WAIT(n)  asm volatile("cp.async.wait_group %0;" :: "n"(n) : "memory")

// ----------------------------------------------------------------------------
// Kernel 0: dtype probe (verified R7 — do not touch)
// ----------------------------------------------------------------------------
__global__ void k_probe(const uint32_t* __restrict__ xw, const uint32_t* __restrict__ ww) {
    const int N = 256;
    int x_bf = 0, w_i32 = 0, w_f32 = 0, w_bf = 0;
    for (int i = 0; i < N; i++) {
        uint32_t u = xw[i];
        uint32_t h0 = u & 0xFFFFu, h1 = u >> 16;
        uint32_t e0 = (h0 >> 7) & 0xFFu, e1 = (h1 >> 7) & 0xFFu;
        bool b0 = (h0 == 0u) || (e0 >= 0x60u && e0 <= 0x82u);
        bool b1 = (h1 == 0u) || (e1 >= 0x60u && e1 <= 0x82u);
        x_bf += (b0 && b1) ? 1 : 0;

        uint32_t w = ww[i];
        uint32_t s = w >> 8;
        w_i32 += (s == 0u || s == 0x00FFFFFFu) ? 1 : 0;
        uint32_t e = (w >> 23) & 0xFFu;
        w_f32 += (w == 0u || (e >= 0x7Fu && e <= 0x86u)) ? 1 : 0;
        uint32_t g0 = w & 0xFFFFu, g1 = w >> 16;
        uint32_t f0 = (g0 >> 7) & 0xFFu, f1 = (g1 >> 7) & 0xFFu;
        bool c0 = (g0 == 0u) || (f0 >= 0x7Fu && f0 <= 0x86u);
        bool c1 = (g1 == 0u) || (f1 >= 0x7Fu && f1 <= 0x86u);
        w_bf += (c0 && c1) ? 1 : 0;
    }
    g_xdtype = (x_bf >= 230) ? 1 : 0;
    int wd = 0;
    if      (w_bf  >= 230) wd = 3;
    else if (w_i32 >= 230) wd = 1;
    else if (w_f32 >= 230) wd = 2;
    g_wdtype = wd;
}

// ----------------------------------------------------------------------------
// Kernel 1: x (f32 or bf16) -> f16   (verified R7)
// ----------------------------------------------------------------------------
__global__ void __launch_bounds__(256) k_convert_x(const void* __restrict__ xv) {
    size_t i = ((size_t)blockIdx.x * 256 + threadIdx.x) * 8;
    uint4 o;
    if (g_xdtype == 0) {
        const float* x = (const float*)xv;
        float4 a = *reinterpret_cast<const float4*>(x + i);
        float4 b = *reinterpret_cast<const float4*>(x + i + 4);
        __half2 h0 = __floats2half2_rn(a.x, a.y);
        __half2 h1 = __floats2half2_rn(a.z, a.w);
        __half2 h2 = __floats2half2_rn(b.x, b.y);
        __half2 h3 = __floats2half2_rn(b.z, b.w);
        o.x = *reinterpret_cast<uint32_t*>(&h0);
        o.y = *reinterpret_cast<uint32_t*>(&h1);
        o.z = *reinterpret_cast<uint32_t*>(&h2);
        o.w = *reinterpret_cast<uint32_t*>(&h3);
    } else {
        const __nv_bfloat16* x = (const __nv_bfloat16*)xv;
        uint4 v = *reinterpret_cast<const uint4*>(x + i);
        const __nv_bfloat16* bp = reinterpret_cast<const __nv_bfloat16*>(&v);
        __half h[8];
        #pragma unroll
        for (int j = 0; j < 8; j++) h[j] = __float2half_rn(__bfloat162float(bp[j]));
        o = *reinterpret_cast<uint4*>(h);
    }
    *reinterpret_cast<uint4*>(g_xh + i) = o;
}

// ----------------------------------------------------------------------------
// Kernel 2: W (int8/int32/f32/bf16, logical [K,N]) -> f16 [N,K]   (verified R7)
// ----------------------------------------------------------------------------
__global__ void __launch_bounds__(256) k_convert_w(const void* __restrict__ wv) {
    __shared__ __half tile[32][33];
    int n0 = blockIdx.x * 32, k0 = blockIdx.y * 32;
    int tx = threadIdx.x, ty = threadIdx.y;   // 32 x 8
    int wd = g_wdtype;
    #pragma unroll
    for (int r = 0; r < 4; r++) {
        int k = k0 + ty + r * 8;
        size_t idx = (size_t)k * DOUT + n0 + tx;
        float v;
        if      (wd == 1) v = (float)((const int*)wv)[idx];
        else if (wd == 2) v = ((const float*)wv)[idx];
        else if (wd == 3) v = __bfloat162float(((const __nv_bfloat16*)wv)[idx]);
        else              v = (float)((const int8_t*)wv)[idx];
        tile[ty + r * 8][tx] = __float2half_rn(v);
    }
    __syncthreads();
    #pragma unroll
    for (int r = 0; r < 4; r++) {
        int n = n0 + ty + r * 8;
        g_wt[(size_t)n * DIN + k0 + tx] = tile[tx][ty + r * 8];
    }
}

// ============================================================================
// GEMM: mma.sync HMMA, CTA 256x128x32, 16 warps (4x4), warp tile 64x32,
//       6-stage cp.async ring, TWO chunks per barrier (superiter):
//       barrier count halved; chunk 2s+1's LDSMs overlap chunk 2s's MMAs
//       via scoreboarding (no barrier between them, no extra registers).
// ============================================================================
#define FBM 256
#define FBN 128
#define FBK 32
#define FSTAGES 6
#define FNCHUNK (DIN / FBK)            // 64
#define FNSUPER (FNCHUNK / 2)          // 32
#define FA_BYTES (FBM * 64)            // 16384
#define FB_BYTES (FBN * 64)            // 8192
#define FSMEM_TOTAL (FSTAGES * (FA_BYTES + FB_BYTES))   // 147456

#define SWZ16(row, c) ((uint32_t)(((c) ^ (((row) >> 1) & 3)) << 4))

#define LDSM4(r0, r1, r2, r3, addr) \
    asm volatile("ldmatrix.sync.aligned.m8n8.x4.shared.b16 {%0,%1,%2,%3}, [%4];" \
                 : "=r"(r0), "=r"(r1), "=r"(r2), "=r"(r3) : "r"(addr))

__device__ __forceinline__ void mma16816(float* c, const uint32_t* a, const uint32_t* b) {
    asm volatile(
        "mma.sync.aligned.m16n8k16.row.col.f32.f16.f16.f32 "
        "{%0,%1,%2,%3}, {%4,%5,%6,%7}, {%8,%9}, {%0,%1,%2,%3};"
        : "+f"(c[0]), "+f"(c[1]), "+f"(c[2]), "+f"(c[3])
        : "r"(a[0]), "r"(a[1]), "r"(a[2]), "r"(a[3]), "r"(b[0]), "r"(b[1]));
}

// Stage loader (512 threads):
//   A: 256 rows x 4 chunks = 1024 cp.async -> 2/thread
//   B: 128 rows x 4 chunks =  512 cp.async -> 1/thread
__device__ __forceinline__ void f_load_stage(uint32_t sbase, int m0, int n0,
                                             int s, int c, int tid) {
    {
        int row = tid >> 1;                      // 0..255
        int c0  = (tid & 1) * 2;                 // chunks c0, c0+1
        uint32_t a_base = sbase + s * FA_BYTES + (uint32_t)row * 64;
        const __half* ag = g_xh + (size_t)(m0 + row) * DIN + c * FBK + c0 * 8;
        cpasync16(a_base + SWZ16(row, c0),     ag);
        cpasync16(a_base + SWZ16(row, c0 + 1), ag + 8);
    }
    {
        int row = tid >> 2;                      // 0..127
        int cc  = tid & 3;                       // chunk 0..3
        uint32_t b_base = sbase + FSTAGES * FA_BYTES + s * FB_BYTES + (uint32_t)row * 64;
        const __half* bg = g_wt + (size_t)(n0 + row) * DIN + c * FBK + cc * 8;
        cpasync16(b_base + SWZ16(row, cc), bg);
    }
}

__global__ void __launch_bounds__(512, 1)
k_gemm_mma(const float* __restrict__ scale, float* __restrict__ out) {
    extern __shared__ __align__(16) char fsm[];
    uint32_t sbase = smem_u32(fsm);
    int tid = threadIdx.x;
    int lane = tid & 31, wid = tid >> 5;
    int wm = wid >> 2;                   // 0..3  (64-row quarter)
    int wn = wid & 3;                    // 0..3  (32-col quarter)

    // n fastest so a wave shares A panels across n-tiles (L2 reuse)
    int n_tile = blockIdx.x & 15;
    int m_tile = blockIdx.x >> 4;
    int m0 = m_tile * FBM;
    int n0 = n_tile * FBN;

    float acc[4][4][4] = {};

    // Prologue: chunks 0..3 into stages 0..3, two commit groups of 2 chunks.
    f_load_stage(sbase, m0, n0, 0, 0, tid);
    f_load_stage(sbase, m0, n0, 1, 1, tid);
    CP_COMMIT();
    f_load_stage(sbase, m0, n0, 2, 2, tid);
    f_load_stage(sbase, m0, n0, 3, 3, tid);
    CP_COMMIT();

    // Hoisted per-thread ldmatrix address components.
    int lr = lane & 15;
    int ch = lane >> 4;                          // 0..1
    uint32_t a_off[4], b_off[2];
    int a_sw[4], b_sw[2];
    #pragma unroll
    for (int mi = 0; mi < 4; mi++) {
        int row = wm * 64 + mi * 16 + lr;
        a_off[mi] = (uint32_t)row * 64;
        a_sw[mi]  = (row >> 1) & 3;
    }
    #pragma unroll
    for (int np = 0; np < 2; np++) {
        int row = wn * 32 + np * 16 + lr;
        b_off[np] = (uint32_t)row * 64;
        b_sw[np]  = (row >> 1) & 3;
    }

    int st0 = 0;                                 // stage of chunk 2s (even, 0/2/4)
    for (int s = 0; s < FNSUPER; s++) {
        // At superiter s the newest commit group is s-1's (chunks 2s+2,2s+3);
        // wait(1) guarantees chunks 2s,2s+1 are complete. Barrier publishes
        // them and retires stages (2s-2)%6,(2s-1)%6 for reuse.
        CP_WAIT(1);
        __syncthreads();

        // Prefetch chunks 2s+4, 2s+5 into stages (st0+4)%6, (st0+5)%6.
        {
            int c4 = 2 * s + 4;
            int ls = st0 + 4; if (ls >= FSTAGES) ls -= FSTAGES;
            if (c4 < FNCHUNK) {
                f_load_stage(sbase, m0, n0, ls, c4, tid);
                int ls1 = ls + 1; if (ls1 >= FSTAGES) ls1 -= FSTAGES;
                f_load_stage(sbase, m0, n0, ls1, c4 + 1, tid);
            }
            CP_COMMIT();                         // empty group near tail keeps
        }                                        // wait_group accounting valid

        // Compute chunks 2s (stage st0) and 2s+1 (stage st0+1), no barrier
        // between them: scoreboard overlaps chunk1 LDSM with chunk0 MMA.
        #pragma unroll
        for (int kc = 0; kc < 2; kc++) {
            int st = st0 + kc;                   // st0 even <= 4, so st0+1 < 6
            uint32_t a_base = sbase + st * FA_BYTES;
            uint32_t b_base = sbase + FSTAGES * FA_BYTES + st * FB_BYTES;

            #pragma unroll
            for (int ks = 0; ks < 2; ks++) {
                int c = ks * 2 + ch;
                uint32_t a[4][4];
                #pragma unroll
                for (int mi = 0; mi < 4; mi++) {
                    uint32_t addr = a_base + a_off[mi] + (uint32_t)((c ^ a_sw[mi]) << 4);
                    LDSM4(a[mi][0], a[mi][1], a[mi][2], a[mi][3], addr);
                }
                uint32_t b[4][2];
                #pragma unroll
                for (int np = 0; np < 2; np++) {
                    uint32_t r0, r1, r2, r3;
                    uint32_t addr = b_base + b_off[np] + (uint32_t)((c ^ b_sw[np]) << 4);
                    LDSM4(r0, r1, r2, r3, addr);
                    b[np * 2 + 0][0] = r0; b[np * 2 + 0][1] = r2;
                    b[np * 2 + 1][0] = r1; b[np * 2 + 1][1] = r3;
                }
                #pragma unroll
                for (int mi = 0; mi < 4; mi++)
                    #pragma unroll
                    for (int ni = 0; ni < 4; ni++)
                        mma16816(acc[mi][ni], a[mi], b[ni]);
            }
        }

        st0 += 2; if (st0 >= FSTAGES) st0 -= FSTAGES;
    }

    // epilogue: * scale (per output column), float2 stores
    #pragma unroll
    for (int mi = 0; mi < 4; mi++) {
        int r0 = m0 + wm * 64 + mi * 16 + (lane >> 2);
        #pragma unroll
        for (int ni = 0; ni < 4; ni++) {
            int col = n0 + wn * 32 + ni * 8 + (lane & 3) * 2;
            float2 sc = *reinterpret_cast<const float2*>(scale + col);
            float2 o0, o1;
            o0.x = acc[mi][ni][0] * sc.x; o0.y = acc[mi][ni][1] * sc.y;
            o1.x = acc[mi][ni][2] * sc.x; o1.y = acc[mi][ni][3] * sc.y;
            *reinterpret_cast<float2*>(out + (size_t)r0 * DOUT + col) = o0;
            *reinterpret_cast<float2*>(out + (size_t)(r0 + 8) * DOUT + col) = o1;
        }
    }
}

// ----------------------------------------------------------------------------
// Launch
// ----------------------------------------------------------------------------
extern "C" void kernel_launch(void* const* d_in, const int* in_sizes, int n_in,
                              void* d_out, int out_size) {
    const void* x = nullptr;
    const float* scale = nullptr;
    const void* w = nullptr;
    for (int i = 0; i < n_in; i++) {
        if (in_sizes[i] == TOKENS * DIN)      x = d_in[i];
        else if (in_sizes[i] == DOUT)         scale = (const float*)d_in[i];
        else if (in_sizes[i] == DIN * DOUT)   w = d_in[i];
    }
    float* out = (float*)d_out;

    k_probe<<<1, 1>>>((const uint32_t*)x, (const uint32_t*)w);
    k_convert_x<<<(TOKENS * DIN) / 8 / 256, 256>>>(x);
    k_convert_w<<<dim3(DOUT / 32, DIN / 32), dim3(32, 8)>>>(w);

    cudaFuncSetAttribute(k_gemm_mma, cudaFuncAttributeMaxDynamicSharedMemorySize, FSMEM_TOTAL);
    cudaFuncSetAttribute(k_gemm_mma, cudaFuncAttributePreferredSharedMemoryCarveout,
                         cudaSharedmemCarveoutMaxShared);
    k_gemm_mma<<<(TOKENS / FBM) * (DOUT / FBN), 512, FSMEM_TOTAL>>>(scale, out);
}

// round 17
// speedup vs baseline: 1.1513x; 1.1513x over previous
#include <cuda_runtime.h>
#include <cuda_fp16.h>
#include <cuda_bf16.h>
#include <cstdint>
#include <cstddef>

// ----------------------------------------------------------------------------
// Problem constants
// ----------------------------------------------------------------------------
#define TOKENS 16384
#define DIN    2048
#define DOUT   2048

// ----------------------------------------------------------------------------
// Scratch (device globals — no allocation allowed)
// ----------------------------------------------------------------------------
__device__ __align__(16) __half g_xh[(size_t)TOKENS * DIN];   // x in fp16      (64 MB)
__device__ __align__(16) __half g_wt[(size_t)DOUT * DIN];     // W^T fp16 [N,K] ( 8 MB)
__device__ int g_xdtype;   // 0 = float32, 1 = bf16
__device__ int g_wdtype;   // 0 = int8, 1 = int32, 2 = float32, 3 = bf16

// ----------------------------------------------------------------------------
// Helpers
// ----------------------------------------------------------------------------
__device__ __forceinline__ uint32_t smem_u32(const void* p) {
    uint32_t a;
    asm("{ .reg .u64 t; cvta.to.shared.u64 t, %1; cvt.u32.u64 %0, t; }" : "=r"(a) : "l"(p));
    return a;
}
__device__ __forceinline__ void cpasync16(uint32_t s, const void* g) {
    asm volatile("cp.async.cg.shared.global [%0], [%1], 16;"
                 :: "r"(s), "l"(__cvta_generic_to_global(g)));
}

#define MBARRIER_INIT(addr, count) \
    asm volatile("mbarrier.init.shared.b64 [%0], %1;" \
                 :: "r"((uint32_t)(addr)), "r"((uint32_t)(count)) : "memory")
#define MBARRIER_ARRIVE(addr) \
    asm volatile("mbarrier.arrive.shared.b64 _, [%0];" \
                 :: "r"((uint32_t)(addr)) : "memory")
// R16 deadlock fix: .noinc — arrive against the PRE-INITIALIZED count when this
// thread's prior cp.asyncs complete. The default (no .noinc) form increments
// the pending count at issue (net zero) and the barrier never flips.
#define CPASYNC_MBAR_ARRIVE(addr) \
    asm volatile("cp.async.mbarrier.arrive.noinc.shared::cta.b64 [%0];" \
                 :: "r"((uint32_t)(addr)) : "memory")

#define MBARRIER_WAIT_PARITY(mbar_smem_addr, phase_parity) do { \
    uint32_t _mbar = (uint32_t)(mbar_smem_addr); \
    uint32_t _parity = (uint32_t)(phase_parity); \
    uint32_t _done; \
    asm volatile( \
        "{\n\t.reg .pred p;\n\t" \
        "mbarrier.try_wait.parity.shared.b64 p, [%1], %2;\n\t" \
        "selp.b32 %0, 1, 0, p;\n\t}" \
        : "=r"(_done) : "r"(_mbar), "r"(_parity) : "memory"); \
    if (!_done) { \
        asm volatile( \
            "{\n\t.reg .pred P1;\n\t" \
            "WAIT_LOOP_%=:\n\t" \
            "mbarrier.try_wait.parity.shared.b64 P1, [%0], %1, 0x989680;\n\t" \
            "@P1 bra.uni WAIT_DONE_%=;\n\t" \
            "bra.uni WAIT_LOOP_%=;\n\t" \
            "WAIT_DONE_%=:\n\t}" \
            :: "r"(_mbar), "r"(_parity) : "memory"); \
    } \
} while (0)

// ----------------------------------------------------------------------------
// Kernel 0: dtype probe (verified R7 — do not touch)
// ----------------------------------------------------------------------------
__global__ void k_probe(const uint32_t* __restrict__ xw, const uint32_t* __restrict__ ww) {
    const int N = 256;
    int x_bf = 0, w_i32 = 0, w_f32 = 0, w_bf = 0;
    for (int i = 0; i < N; i++) {
        uint32_t u = xw[i];
        uint32_t h0 = u & 0xFFFFu, h1 = u >> 16;
        uint32_t e0 = (h0 >> 7) & 0xFFu, e1 = (h1 >> 7) & 0xFFu;
        bool b0 = (h0 == 0u) || (e0 >= 0x60u && e0 <= 0x82u);
        bool b1 = (h1 == 0u) || (e1 >= 0x60u && e1 <= 0x82u);
        x_bf += (b0 && b1) ? 1 : 0;

        uint32_t w = ww[i];
        uint32_t s = w >> 8;
        w_i32 += (s == 0u || s == 0x00FFFFFFu) ? 1 : 0;
        uint32_t e = (w >> 23) & 0xFFu;
        w_f32 += (w == 0u || (e >= 0x7Fu && e <= 0x86u)) ? 1 : 0;
        uint32_t g0 = w & 0xFFFFu, g1 = w >> 16;
        uint32_t f0 = (g0 >> 7) & 0xFFu, f1 = (g1 >> 7) & 0xFFu;
        bool c0 = (g0 == 0u) || (f0 >= 0x7Fu && f0 <= 0x86u);
        bool c1 = (g1 == 0u) || (f1 >= 0x7Fu && f1 <= 0x86u);
        w_bf += (c0 && c1) ? 1 : 0;
    }
    g_xdtype = (x_bf >= 230) ? 1 : 0;
    int wd = 0;
    if      (w_bf  >= 230) wd = 3;
    else if (w_i32 >= 230) wd = 1;
    else if (w_f32 >= 230) wd = 2;
    g_wdtype = wd;
}

// ----------------------------------------------------------------------------
// Kernel 1: x (f32 or bf16) -> f16   (verified R7)
// ----------------------------------------------------------------------------
__global__ void __launch_bounds__(256) k_convert_x(const void* __restrict__ xv) {
    size_t i = ((size_t)blockIdx.x * 256 + threadIdx.x) * 8;
    uint4 o;
    if (g_xdtype == 0) {
        const float* x = (const float*)xv;
        float4 a = *reinterpret_cast<const float4*>(x + i);
        float4 b = *reinterpret_cast<const float4*>(x + i + 4);
        __half2 h0 = __floats2half2_rn(a.x, a.y);
        __half2 h1 = __floats2half2_rn(a.z, a.w);
        __half2 h2 = __floats2half2_rn(b.x, b.y);
        __half2 h3 = __floats2half2_rn(b.z, b.w);
        o.x = *reinterpret_cast<uint32_t*>(&h0);
        o.y = *reinterpret_cast<uint32_t*>(&h1);
        o.z = *reinterpret_cast<uint32_t*>(&h2);
        o.w = *reinterpret_cast<uint32_t*>(&h3);
    } else {
        const __nv_bfloat16* x = (const __nv_bfloat16*)xv;
        uint4 v = *reinterpret_cast<const uint4*>(x + i);
        const __nv_bfloat16* bp = reinterpret_cast<const __nv_bfloat16*>(&v);
        __half h[8];
        #pragma unroll
        for (int j = 0; j < 8; j++) h[j] = __float2half_rn(__bfloat162float(bp[j]));
        o = *reinterpret_cast<uint4*>(h);
    }
    *reinterpret_cast<uint4*>(g_xh + i) = o;
}

// ----------------------------------------------------------------------------
// Kernel 2: W (int8/int32/f32/bf16, logical [K,N]) -> f16 [N,K]   (verified R7)
// ----------------------------------------------------------------------------
__global__ void __launch_bounds__(256) k_convert_w(const void* __restrict__ wv) {
    __shared__ __half tile[32][33];
    int n0 = blockIdx.x * 32, k0 = blockIdx.y * 32;
    int tx = threadIdx.x, ty = threadIdx.y;   // 32 x 8
    int wd = g_wdtype;
    #pragma unroll
    for (int r = 0; r < 4; r++) {
        int k = k0 + ty + r * 8;
        size_t idx = (size_t)k * DOUT + n0 + tx;
        float v;
        if      (wd == 1) v = (float)((const int*)wv)[idx];
        else if (wd == 2) v = ((const float*)wv)[idx];
        else if (wd == 3) v = __bfloat162float(((const __nv_bfloat16*)wv)[idx]);
        else              v = (float)((const int8_t*)wv)[idx];
        tile[ty + r * 8][tx] = __float2half_rn(v);
    }
    __syncthreads();
    #pragma unroll
    for (int r = 0; r < 4; r++) {
        int n = n0 + ty + r * 8;
        g_wt[(size_t)n * DIN + k0 + tx] = tile[tx][ty + r * 8];
    }
}

// ============================================================================
// GEMM: mma.sync HMMA, CTA 256x128x32, 16 warps (4x4), warp tile 64x32,
//       6-stage mbarrier producer/consumer ring, NO __syncthreads in the
//       mainloop: warps free-run across chunk boundaries, desynchronize, and
//       keep the tensor pipe continuously fed.
// ============================================================================
#define FBM 256
#define FBN 128
#define FBK 32
#define FSTAGES 6
#define FNCHUNK (DIN / FBK)            // 64
#define FA_BYTES (FBM * 64)            // 16384
#define FB_BYTES (FBN * 64)            // 8192
#define FTILE_BYTES (FSTAGES * (FA_BYTES + FB_BYTES))   // 147456
#define FSMEM_TOTAL (FTILE_BYTES + 128)                 // + mbarriers
#define NTHREADS 512

#define SWZ16(row, c) ((uint32_t)(((c) ^ (((row) >> 1) & 3)) << 4))

#define LDSM4(r0, r1, r2, r3, addr) \
    asm volatile("ldmatrix.sync.aligned.m8n8.x4.shared.b16 {%0,%1,%2,%3}, [%4];" \
                 : "=r"(r0), "=r"(r1), "=r"(r2), "=r"(r3) : "r"(addr))

__device__ __forceinline__ void mma16816(float* c, const uint32_t* a, const uint32_t* b) {
    asm volatile(
        "mma.sync.aligned.m16n8k16.row.col.f32.f16.f16.f32 "
        "{%0,%1,%2,%3}, {%4,%5,%6,%7}, {%8,%9}, {%0,%1,%2,%3};"
        : "+f"(c[0]), "+f"(c[1]), "+f"(c[2]), "+f"(c[3])
        : "r"(a[0]), "r"(a[1]), "r"(a[2]), "r"(a[3]), "r"(b[0]), "r"(b[1]));
}

// Stage loader (512 threads): A 2 chunks/thread + B 1 chunk/thread (16B each).
__device__ __forceinline__ void f_load_stage(uint32_t sbase, int m0, int n0,
                                             int s, int c, int tid) {
    {
        int row = tid >> 1;                      // 0..255
        int c0  = (tid & 1) * 2;                 // chunks c0, c0+1
        uint32_t a_base = sbase + s * FA_BYTES + (uint32_t)row * 64;
        const __half* ag = g_xh + (size_t)(m0 + row) * DIN + c * FBK + c0 * 8;
        cpasync16(a_base + SWZ16(row, c0),     ag);
        cpasync16(a_base + SWZ16(row, c0 + 1), ag + 8);
    }
    {
        int row = tid >> 2;                      // 0..127
        int cc  = tid & 3;                       // chunk 0..3
        uint32_t b_base = sbase + FSTAGES * FA_BYTES + s * FB_BYTES + (uint32_t)row * 64;
        const __half* bg = g_wt + (size_t)(n0 + row) * DIN + c * FBK + cc * 8;
        cpasync16(b_base + SWZ16(row, cc), bg);
    }
}

__global__ void __launch_bounds__(512, 1)
k_gemm_mma(const float* __restrict__ scale, float* __restrict__ out) {
    extern __shared__ __align__(16) char fsm[];
    uint32_t sbase = smem_u32(fsm);
    uint32_t mb_full  = sbase + FTILE_BYTES;        // full[s]  at +8*s
    uint32_t mb_empty = sbase + FTILE_BYTES + 48;   // empty[s] at +8*s
    int tid = threadIdx.x;
    int lane = tid & 31, wid = tid >> 5;
    int wm = wid >> 2;                   // 0..3  (64-row quarter)
    int wn = wid & 3;                    // 0..3  (32-col quarter)

    // n fastest so a wave shares A panels across n-tiles (L2 reuse)
    int n_tile = blockIdx.x & 15;
    int m_tile = blockIdx.x >> 4;
    int m0 = m_tile * FBM;
    int n0 = n_tile * FBN;

    if (tid == 0) {
        #pragma unroll
        for (int s = 0; s < FSTAGES; s++) {
            MBARRIER_INIT(mb_full  + s * 8, NTHREADS);
            MBARRIER_INIT(mb_empty + s * 8, NTHREADS);
        }
    }
    __syncthreads();    // publish mbarrier init (only CTA-wide barrier used)

    float acc[4][4][4] = {};

    // Producer cursor: next stage to fill; phase starts FLIPPED (1) so the
    // first FSTAGES empty-waits pass immediately (ptx_helpers convention).
    int prod_st = 0, prod_ph = 1;
    // Consumer cursor.
    int cons_st = 0, cons_ph = 0;

    // Prologue: fill 5 of 6 stages (chunks 0..4).
    #pragma unroll
    for (int c = 0; c < FSTAGES - 1; c++) {
        MBARRIER_WAIT_PARITY(mb_empty + prod_st * 8, prod_ph);
        f_load_stage(sbase, m0, n0, prod_st, c, tid);
        CPASYNC_MBAR_ARRIVE(mb_full + prod_st * 8);
        if (++prod_st == FSTAGES) { prod_st = 0; prod_ph ^= 1; }
    }

    // Hoisted per-thread ldmatrix address components.
    int lr = lane & 15;
    int ch = lane >> 4;                          // 0..1
    uint32_t a_off[4], b_off[2];
    int a_sw[4], b_sw[2];
    #pragma unroll
    for (int mi = 0; mi < 4; mi++) {
        int row = wm * 64 + mi * 16 + lr;
        a_off[mi] = (uint32_t)row * 64;
        a_sw[mi]  = (row >> 1) & 3;
    }
    #pragma unroll
    for (int np = 0; np < 2; np++) {
        int row = wn * 32 + np * 16 + lr;
        b_off[np] = (uint32_t)row * 64;
        b_sw[np]  = (row >> 1) & 3;
    }

    for (int i = 0; i < FNCHUNK; i++) {
        // ---- consume chunk i from stage cons_st ----
        MBARRIER_WAIT_PARITY(mb_full + cons_st * 8, cons_ph);

        uint32_t a_base = sbase + cons_st * FA_BYTES;
        uint32_t b_base = sbase + FSTAGES * FA_BYTES + cons_st * FB_BYTES;

        #pragma unroll
        for (int ks = 0; ks < 2; ks++) {
            int c = ks * 2 + ch;
            uint32_t a[4][4];
            #pragma unroll
            for (int mi = 0; mi < 4; mi++) {
                uint32_t addr = a_base + a_off[mi] + (uint32_t)((c ^ a_sw[mi]) << 4);
                LDSM4(a[mi][0], a[mi][1], a[mi][2], a[mi][3], addr);
            }
            uint32_t b[4][2];
            #pragma unroll
            for (int np = 0; np < 2; np++) {
                uint32_t r0, r1, r2, r3;
                uint32_t addr = b_base + b_off[np] + (uint32_t)((c ^ b_sw[np]) << 4);
                LDSM4(r0, r1, r2, r3, addr);
                b[np * 2 + 0][0] = r0; b[np * 2 + 0][1] = r2;
                b[np * 2 + 1][0] = r1; b[np * 2 + 1][1] = r3;
            }
            #pragma unroll
            for (int mi = 0; mi < 4; mi++)
                #pragma unroll
                for (int ni = 0; ni < 4; ni++)
                    mma16816(acc[mi][ni], a[mi], b[ni]);
        }

        // Done reading stage: release it for the producer side.
        MBARRIER_ARRIVE(mb_empty + cons_st * 8);
        if (++cons_st == FSTAGES) { cons_st = 0; cons_ph ^= 1; }

        // ---- produce chunk i+5 into the ring ----
        int nc = i + FSTAGES - 1;
        if (nc < FNCHUNK) {
            MBARRIER_WAIT_PARITY(mb_empty + prod_st * 8, prod_ph);
            f_load_stage(sbase, m0, n0, prod_st, nc, tid);
            CPASYNC_MBAR_ARRIVE(mb_full + prod_st * 8);
            if (++prod_st == FSTAGES) { prod_st = 0; prod_ph ^= 1; }
        }
    }

    // epilogue: * scale (per output column), float2 stores
    #pragma unroll
    for (int mi = 0; mi < 4; mi++) {
        int r0 = m0 + wm * 64 + mi * 16 + (lane >> 2);
        #pragma unroll
        for (int ni = 0; ni < 4; ni++) {
            int col = n0 + wn * 32 + ni * 8 + (lane & 3) * 2;
            float2 sc = *reinterpret_cast<const float2*>(scale + col);
            float2 o0, o1;
            o0.x = acc[mi][ni][0] * sc.x; o0.y = acc[mi][ni][1] * sc.y;
            o1.x = acc[mi][ni][2] * sc.x; o1.y = acc[mi][ni][3] * sc.y;
            *reinterpret_cast<float2*>(out + (size_t)r0 * DOUT + col) = o0;
            *reinterpret_cast<float2*>(out + (size_t)(r0 + 8) * DOUT + col) = o1;
        }
    }
}

// ----------------------------------------------------------------------------
// Launch
// ----------------------------------------------------------------------------
extern "C" void kernel_launch(void* const* d_in, const int* in_sizes, int n_in,
                              void* d_out, int out_size) {
    const void* x = nullptr;
    const float* scale = nullptr;
    const void* w = nullptr;
    for (int i = 0; i < n_in; i++) {
        if (in_sizes[i] == TOKENS * DIN)      x = d_in[i];
        else if (in_sizes[i] == DOUT)         scale = (const float*)d_in[i];
        else if (in_sizes[i] == DIN * DOUT)   w = d_in[i];
    }
    float* out = (float*)d_out;

    k_probe<<<1, 1>>>((const uint32_t*)x, (const uint32_t*)w);
    k_convert_x<<<(TOKENS * DIN) / 8 / 256, 256>>>(x);
    k_convert_w<<<dim3(DOUT / 32, DIN / 32), dim3(32, 8)>>>(w);

    cudaFuncSetAttribute(k_gemm_mma, cudaFuncAttributeMaxDynamicSharedMemorySize, FSMEM_TOTAL);
    cudaFuncSetAttribute(k_gemm_mma, cudaFuncAttributePreferredSharedMemoryCarveout,
                         cudaSharedmemCarveoutMaxShared);
    k_gemm_mma<<<(TOKENS / FBM) * (DOUT / FBN), NTHREADS, FSMEM_TOTAL>>>(scale, out);
}